// round 9
// baseline (speedup 1.0000x reference)
#include <cuda_runtime.h>

// MMD_53008486367839 — batched persistence-diagram MMD with RBF kernel.
// B=64, N=M=1024, WIDTH=DECAY=1.
//
// Mercer feature expansion (validated R7/R8): on u,v in [0,1),
//   K(p,q) = e^{-|p|^2} e^{-|q|^2} sum_{a+b<=D} (2ux)^a (2vy)^b /(a! b!)
//   mmd_b  = sum_{a+b<=D} c_ab F_ab^2,  c_ab = 2^(a+b)/(a! b!),
//   F_ab   = sum_i s_i e^{-u_i^2-v_i^2} u_i^a v_i^b,
//   s_i = +lifetime (X), -lifetime (Y).     O(B*P*R) FMAs, no pairwise EX2.
//
// R9: SINGLE launch. 512 blocks (one 256-point tile each) write per-block
// feature partials with plain stores (no zeroing, no float atomics). The
// last-finishing block (threadfence-reduction counter) does the full
// c*F^2-weighted reduce with float4 loads and writes out[0] directly.

#define BATCH 64
#define NPTS  1024
#define P     2048
#define D     20            // total degree of expansion
#define NF    231           // (D+1)(D+2)/2 features
#define NFP   232           // padded (float4-friendly)
#define NQ    58            // NFP/4
#define PB    8             // blocks per batch
#define TILE  256           // points per block
#define GRID  (BATCH * PB)  // 512
#define NPOW  (D + 1)
#define STR   260           // shared row stride (words, 16B-multiple)

__device__ float g_part[GRID][NFP];
__device__ int   g_ctr;     // zero-initialized; reset by the last block each call

__constant__ float c_inv_fact[NPOW] = {
    1.0f, 1.0f, 0.5f, 1.6666666666666666e-01f, 4.1666666666666664e-02f,
    8.3333333333333332e-03f, 1.3888888888888889e-03f, 1.9841269841269841e-04f,
    2.4801587301587302e-05f, 2.7557319223985893e-06f, 2.7557319223985888e-07f,
    2.5052108385441720e-08f, 2.0876756987868100e-09f, 1.6059043836821613e-10f,
    1.1470745597729725e-11f, 7.6471637318198164e-13f, 4.7794773323873853e-14f,
    2.8114572543455206e-15f, 1.5619206968586226e-16f, 8.2206352466243295e-18f,
    4.1103176233121648e-19f};

__device__ __forceinline__ float ex2f_(float x) {
    float y;
    asm("ex2.approx.ftz.f32 %0, %1;" : "=f"(y) : "f"(x));
    return y;
}

// k -> (a, b), a-major enumeration of {(a,b): a+b<=D}
__device__ __forceinline__ void feat_ab(int k, int& fa, int& fb) {
    int a = 0;
    #pragma unroll 1
    while (k >= (D + 1 - a)) { k -= (D + 1 - a); a++; }
    fa = a; fb = k;
}

__global__ void __launch_bounds__(256) mmd_fused(const float* __restrict__ X,
                                                 const float* __restrict__ Y,
                                                 const float* __restrict__ weights,
                                                 const float* __restrict__ num_samples,
                                                 float* __restrict__ out) {
    __shared__ __align__(16) float spu[NPOW][STR];  // s*e^{-u^2-v^2} * u^a
    __shared__ __align__(16) float spv[NPOW][STR];  // v^b
    __shared__ int   s_rank;
    __shared__ float sc[NFP];        // reduce: c coefficients
    __shared__ float sws[BATCH];     // reduce: weights[b]/ns^2
    __shared__ float warp_sums[8];

    const int blk   = blockIdx.x;
    const int b     = blk >> 3;          // / PB
    const int chunk = blk & (PB - 1);
    const int t     = threadIdx.x;

    // ---- phase 1: transform my point, write folded power chains ----
    {
        int p = chunk * TILE + t;
        float u, v, s;
        if (p < NPTS) {
            float2 xy = __ldg((const float2*)(X + ((size_t)b * NPTS + p) * 2));
            u = xy.x; v = xy.y - xy.x; s = v;
        } else {
            float2 xy = __ldg((const float2*)(Y + ((size_t)b * NPTS + (p - NPTS)) * 2));
            u = xy.x; v = xy.y - xy.x; s = -v;
        }
        const float LOG2E = 1.4426950408889634f;
        float m  = fmaf(u, u, v * v);
        float ps = s * ex2f_(-m * LOG2E);           // s * exp(-(u^2+v^2))

        float pw = ps;
        spu[0][t] = pw;
        #pragma unroll
        for (int a = 1; a < NPOW; a++) { pw *= u; spu[a][t] = pw; }
        pw = 1.f;
        spv[0][t] = 1.f;
        #pragma unroll
        for (int bb = 1; bb < NPOW; bb++) { pw *= v; spv[bb][t] = pw; }
    }
    __syncthreads();

    // ---- phase 2: thread t accumulates feature (a,b) over the tile ----
    {
        int fa, fb;
        feat_ab(t < NF ? t : 0, fa, fb);
        float a0 = 0.f, a1 = 0.f, a2 = 0.f, a3 = 0.f;
        if (t < NF) {
            const float4* pua = (const float4*)&spu[fa][0];
            const float4* pvb = (const float4*)&spv[fb][0];
            #pragma unroll 8
            for (int j = 0; j < TILE / 4; j++) {
                float4 A  = pua[j];
                float4 Bv = pvb[j];
                a0 = fmaf(A.x, Bv.x, a0);
                a1 = fmaf(A.y, Bv.y, a1);
                a2 = fmaf(A.z, Bv.z, a2);
                a3 = fmaf(A.w, Bv.w, a3);
            }
        }
        if (t < NFP)
            g_part[blk][t] = (t < NF) ? ((a0 + a1) + (a2 + a3)) : 0.0f;
    }

    // ---- completion count (threadfence-reduction pattern) ----
    __threadfence();
    __syncthreads();
    if (t == 0) s_rank = atomicAdd(&g_ctr, 1);
    __syncthreads();
    if (s_rank != GRID - 1) return;

    // ================= last block: full reduce =================
    __threadfence();  // acquire all partials

    // precompute coefficients and per-batch weights in shared
    if (t < NFP) {
        float c = 0.f;
        if (t < NF) {
            int fa, fb;
            feat_ab(t, fa, fb);
            c = exp2f((float)(fa + fb)) * c_inv_fact[fa] * c_inv_fact[fb];
        }
        sc[t] = c;
    }
    if (t < BATCH) {
        float ns = __ldg(&num_samples[t]);
        sws[t] = __ldg(&weights[t]) / (ns * ns);
    }
    __syncthreads();

    const float4* P4 = (const float4*)g_part;   // [GRID][NQ]
    float val = 0.f;
    #pragma unroll 1
    for (int qi = t; qi < BATCH * NQ; qi += 256) {
        int b2 = qi / NQ;
        int q  = qi - b2 * NQ;
        float4 F = make_float4(0.f, 0.f, 0.f, 0.f);
        #pragma unroll
        for (int pp = 0; pp < PB; pp++) {
            float4 x = P4[(size_t)(b2 * PB + pp) * NQ + q];
            F.x += x.x; F.y += x.y; F.z += x.z; F.w += x.w;
        }
        int k0 = q * 4;
        float term = sc[k0 + 0] * F.x * F.x;
        term = fmaf(sc[k0 + 1] * F.y, F.y, term);
        term = fmaf(sc[k0 + 2] * F.z, F.z, term);
        term = fmaf(sc[k0 + 3] * F.w, F.w, term);
        val = fmaf(sws[b2], term, val);
    }

    #pragma unroll
    for (int o = 16; o > 0; o >>= 1)
        val += __shfl_down_sync(0xFFFFFFFFu, val, o);
    int lane = t & 31, wid = t >> 5;
    if (lane == 0) warp_sums[wid] = val;
    __syncthreads();

    if (t == 0) {
        float bs = 0.f;
        #pragma unroll
        for (int w = 0; w < 8; w++) bs += warp_sums[w];
        out[0] = bs;
        g_ctr  = 0;          // reset for next graph replay
    }
}

// ---------------------------------------------------------------------------
extern "C" void kernel_launch(void* const* d_in, const int* in_sizes, int n_in,
                              void* d_out, int out_size) {
    const float* X  = (const float*)d_in[0];
    const float* Y  = (const float*)d_in[1];
    const float* w  = (const float*)d_in[2];
    const float* ns = (const float*)d_in[3];
    float* out = (float*)d_out;

    mmd_fused<<<GRID, 256>>>(X, Y, w, ns, out);
}